// round 1
// baseline (speedup 1.0000x reference)
#include <cuda_runtime.h>
#include <math.h>

#define B_   2
#define S_   2048
#define H_   16
#define DK_  64
#define DM_  1024
#define M_   (B_ * S_)   // 4096

// Scratch (device globals — no allocation allowed in kernel_launch)
__device__ float g_Q[B_ * H_ * S_ * DK_];      // [B,H,S,64]
__device__ float g_K[B_ * H_ * S_ * DK_];
__device__ float g_V[B_ * H_ * S_ * DK_];
__device__ float g_attn[(size_t)M_ * DM_];     // [B,S,1024]

// ----------------------------------------------------------------------------
// GEMM: C = A @ W + bias.  A:[M,1024] row-major, W:[1024,1024] row-major.
// mode 0/1/2: write to g_Q/g_K/g_V in head-split layout [B,H,S,64]
// mode 3:     A = g_attn, write plain [M,1024] to Cext
// 64x64 tile, BK=16, 256 threads, 4x4 micro-tile per thread.
// ----------------------------------------------------------------------------
__global__ void __launch_bounds__(256) gemm64(const float* __restrict__ Aext,
                                              const float* __restrict__ W,
                                              const float* __restrict__ bias,
                                              float* __restrict__ Cext,
                                              int mode)
{
    const int K = DM_, N = DM_;
    __shared__ __align__(16) float As[16][68];   // transposed A tile: As[k][m]
    __shared__ __align__(16) float Bs[16][68];   // Bs[k][n]

    const float* A = (mode == 3) ? g_attn : Aext;

    const int t  = threadIdx.x;
    const int tx = t & 15;          // 0..15 -> 4 output cols each
    const int ty = t >> 4;          // 0..15 -> 4 output rows each
    const int row0 = blockIdx.y * 64;
    const int col0 = blockIdx.x * 64;

    const int ar = t >> 2, ak = (t & 3) << 2;    // A-tile load coords
    const int br = t >> 4, bc = (t & 15) << 2;   // B-tile load coords

    float acc[4][4] = {};

    for (int k0 = 0; k0 < K; k0 += 16) {
        float4 va = *reinterpret_cast<const float4*>(A + (size_t)(row0 + ar) * K + k0 + ak);
        As[ak + 0][ar] = va.x;
        As[ak + 1][ar] = va.y;
        As[ak + 2][ar] = va.z;
        As[ak + 3][ar] = va.w;
        *reinterpret_cast<float4*>(&Bs[br][bc]) =
            *reinterpret_cast<const float4*>(W + (size_t)(k0 + br) * N + col0 + bc);
        __syncthreads();

        #pragma unroll
        for (int kk = 0; kk < 16; kk++) {
            float4 a = *reinterpret_cast<const float4*>(&As[kk][ty << 2]);
            float4 b = *reinterpret_cast<const float4*>(&Bs[kk][tx << 2]);
            float av[4] = {a.x, a.y, a.z, a.w};
            float bv[4] = {b.x, b.y, b.z, b.w};
            #pragma unroll
            for (int i = 0; i < 4; i++)
                #pragma unroll
                for (int j = 0; j < 4; j++)
                    acc[i][j] = fmaf(av[i], bv[j], acc[i][j]);
        }
        __syncthreads();
    }

    float bvals[4];
    #pragma unroll
    for (int j = 0; j < 4; j++) bvals[j] = bias[col0 + (tx << 2) + j];

    if (mode < 3) {
        float* Cbase = (mode == 0) ? g_Q : (mode == 1) ? g_K : g_V;
        const int h = col0 >> 6;               // 64 cols per block == one head
        #pragma unroll
        for (int i = 0; i < 4; i++) {
            int row = row0 + (ty << 2) + i;
            int b = row >> 11;                 // row / 2048
            int s = row & (S_ - 1);
            float4 v = make_float4(acc[i][0] + bvals[0], acc[i][1] + bvals[1],
                                   acc[i][2] + bvals[2], acc[i][3] + bvals[3]);
            *reinterpret_cast<float4*>(Cbase + ((size_t)((b * H_ + h) * S_ + s)) * DK_ + (tx << 2)) = v;
        }
    } else {
        #pragma unroll
        for (int i = 0; i < 4; i++) {
            int row = row0 + (ty << 2) + i;
            float4 v = make_float4(acc[i][0] + bvals[0], acc[i][1] + bvals[1],
                                   acc[i][2] + bvals[2], acc[i][3] + bvals[3]);
            *reinterpret_cast<float4*>(Cext + (size_t)row * N + col0 + (tx << 2)) = v;
        }
    }
}

// ----------------------------------------------------------------------------
// Flash attention, causal. One CTA = 64 query rows of one (b,h).
// 256 threads: thread (tx,ty) owns 4x4 block of the 64x64 S/P tile
// (rows ty*4.., key-cols / d-cols tx*4..). Row reductions are half-warp
// shuffles (tx spans lanes 0..15 / 16..31).
// Tiles are 64-aligned, so only the kt==qs tile needs causal masking.
// ----------------------------------------------------------------------------
__global__ void __launch_bounds__(256) attn64()
{
    extern __shared__ __align__(16) float sh[];
    float* Qs = sh;                 // [64 d][68 r]  (d-major, transposed)
    float* Ks = Qs + 64 * 68;       // [64 d][68 c]
    float* Vs = Ks + 64 * 68;       // [64 k][68 d]
    float* Ps = Vs + 64 * 68;       // [64 k(c)][68 r] (transposed P)

    const int qb = blockIdx.x;
    const int bh = blockIdx.y;
    const int qs = qb * 64;
    const int t  = threadIdx.x;
    const int tx = t & 15, ty = t >> 4;

    const float* Qg = g_Q + (size_t)bh * S_ * DK_;
    const float* Kg = g_K + (size_t)bh * S_ * DK_;
    const float* Vg = g_V + (size_t)bh * S_ * DK_;

    // Load Q tile (transposed into Qs[d][r])
    {
        const int d4 = (t & 15) << 2;
        const int r0 = t >> 4;
        #pragma unroll
        for (int rep = 0; rep < 4; rep++) {
            int r = r0 + rep * 16;
            float4 v = *reinterpret_cast<const float4*>(Qg + (size_t)(qs + r) * DK_ + d4);
            Qs[(d4 + 0) * 68 + r] = v.x;
            Qs[(d4 + 1) * 68 + r] = v.y;
            Qs[(d4 + 2) * 68 + r] = v.z;
            Qs[(d4 + 3) * 68 + r] = v.w;
        }
    }

    float o[4][4] = {};
    float m[4], l[4];
    #pragma unroll
    for (int i = 0; i < 4; i++) { m[i] = -INFINITY; l[i] = 0.f; }

    for (int kt = 0; kt <= qs; kt += 64) {
        __syncthreads();  // prior-iteration consumers of Ks/Vs/Ps done (also covers Q-load on iter 0)

        // Load K (transposed) and V (direct)
        {
            const int d4 = (t & 15) << 2;
            const int r0 = t >> 4;
            #pragma unroll
            for (int rep = 0; rep < 4; rep++) {
                int r = r0 + rep * 16;
                float4 kv = *reinterpret_cast<const float4*>(Kg + (size_t)(kt + r) * DK_ + d4);
                Ks[(d4 + 0) * 68 + r] = kv.x;
                Ks[(d4 + 1) * 68 + r] = kv.y;
                Ks[(d4 + 2) * 68 + r] = kv.z;
                Ks[(d4 + 3) * 68 + r] = kv.w;
                float4 vv = *reinterpret_cast<const float4*>(Vg + (size_t)(kt + r) * DK_ + d4);
                *reinterpret_cast<float4*>(&Vs[r * 68 + d4]) = vv;
            }
        }
        __syncthreads();

        // S = Q K^T (64x64, 4x4 per thread)
        float s[4][4] = {};
        #pragma unroll 8
        for (int d = 0; d < 64; d++) {
            float4 a = *reinterpret_cast<const float4*>(&Qs[d * 68 + (ty << 2)]);
            float4 b = *reinterpret_cast<const float4*>(&Ks[d * 68 + (tx << 2)]);
            float av[4] = {a.x, a.y, a.z, a.w};
            float bv[4] = {b.x, b.y, b.z, b.w};
            #pragma unroll
            for (int i = 0; i < 4; i++)
                #pragma unroll
                for (int j = 0; j < 4; j++)
                    s[i][j] = fmaf(av[i], bv[j], s[i][j]);
        }

        const bool diag = (kt == qs);
        #pragma unroll
        for (int i = 0; i < 4; i++) {
            int r = (ty << 2) + i;
            #pragma unroll
            for (int j = 0; j < 4; j++) {
                int c = (tx << 2) + j;
                float val = s[i][j] * 0.125f;        // 1/sqrt(64)
                if (diag && c > r) val = -INFINITY;
                s[i][j] = val;
            }
            // row max across half-warp (tx = 0..15)
            float mx = fmaxf(fmaxf(s[i][0], s[i][1]), fmaxf(s[i][2], s[i][3]));
            #pragma unroll
            for (int off = 8; off; off >>= 1)
                mx = fmaxf(mx, __shfl_xor_sync(0xffffffffu, mx, off));
            float mnew  = fmaxf(m[i], mx);
            float alpha = __expf(m[i] - mnew);       // m[i]=-inf -> 0, safe
            float rs = 0.f;
            #pragma unroll
            for (int j = 0; j < 4; j++) {
                float p = __expf(s[i][j] - mnew);    // masked -> exp(-inf)=0
                s[i][j] = p;
                rs += p;
            }
            #pragma unroll
            for (int off = 8; off; off >>= 1)
                rs += __shfl_xor_sync(0xffffffffu, rs, off);
            l[i] = l[i] * alpha + rs;
            m[i] = mnew;
            #pragma unroll
            for (int j = 0; j < 4; j++) o[i][j] *= alpha;
            // write P transposed: Ps[c][r]
            #pragma unroll
            for (int j = 0; j < 4; j++)
                Ps[((tx << 2) + j) * 68 + (ty << 2) + i] = s[i][j];
        }
        __syncthreads();

        // O += P @ V
        #pragma unroll 8
        for (int k = 0; k < 64; k++) {
            float4 a = *reinterpret_cast<const float4*>(&Ps[k * 68 + (ty << 2)]);
            float4 b = *reinterpret_cast<const float4*>(&Vs[k * 68 + (tx << 2)]);
            float av[4] = {a.x, a.y, a.z, a.w};
            float bv[4] = {b.x, b.y, b.z, b.w};
            #pragma unroll
            for (int i = 0; i < 4; i++)
                #pragma unroll
                for (int j = 0; j < 4; j++)
                    o[i][j] = fmaf(av[i], bv[j], o[i][j]);
        }
    }

    // Epilogue: normalize and write attn in [B,S,1024] layout
    const int b = bh >> 4, h = bh & 15;
    #pragma unroll
    for (int i = 0; i < 4; i++) {
        float inv = 1.0f / l[i];
        int row = qs + (ty << 2) + i;
        float4 v = make_float4(o[i][0] * inv, o[i][1] * inv, o[i][2] * inv, o[i][3] * inv);
        *reinterpret_cast<float4*>(g_attn + ((size_t)(b * S_ + row)) * DM_ + h * DK_ + (tx << 2)) = v;
    }
}

// ----------------------------------------------------------------------------
extern "C" void kernel_launch(void* const* d_in, const int* in_sizes, int n_in,
                              void* d_out, int out_size)
{
    const float* query = (const float*)d_in[0];
    const float* key   = (const float*)d_in[1];
    const float* value = (const float*)d_in[2];
    // d_in[3] = mask (causal by construction; implemented analytically)
    const float* Wq = (const float*)d_in[4];
    const float* bq = (const float*)d_in[5];
    const float* Wk = (const float*)d_in[6];
    const float* bk = (const float*)d_in[7];
    const float* Wv = (const float*)d_in[8];
    const float* bv = (const float*)d_in[9];
    const float* Wo = (const float*)d_in[10];
    const float* bo = (const float*)d_in[11];
    float* out = (float*)d_out;

    const int attn_smem = 4 * 64 * 68 * (int)sizeof(float);  // 69632 B
    cudaFuncSetAttribute(attn64, cudaFuncAttributeMaxDynamicSharedMemorySize, attn_smem);

    dim3 gproj(DM_ / 64, M_ / 64);
    gemm64<<<gproj, 256>>>(query, Wq, bq, nullptr, 0);
    gemm64<<<gproj, 256>>>(key,   Wk, bk, nullptr, 1);
    gemm64<<<gproj, 256>>>(value, Wv, bv, nullptr, 2);
    attn64<<<dim3(S_ / 64, B_ * H_), 256, attn_smem>>>();
    gemm64<<<gproj, 256>>>(nullptr, Wo, bo, out, 3);
}

// round 3
// speedup vs baseline: 1.7034x; 1.7034x over previous
#include <cuda_runtime.h>
#include <cuda_bf16.h>
#include <math.h>
#include <cstdint>

#define B_   2
#define S_   2048
#define H_   16
#define DK_  64
#define DM_  1024
#define M_   (B_ * S_)   // 4096

// ---------------------------------------------------------------------------
// PTX helpers — sm_80+ portable (harness PTX target is sm_103 WITHOUT 'a',
// so tcgen05/TMEM are unavailable; mma.sync/ldmatrix/cp.async are the path).
// ---------------------------------------------------------------------------
__device__ __forceinline__ uint32_t smem_u32(const void* p) {
    uint32_t a;
    asm("{ .reg .u64 t; cvta.to.shared.u64 t, %1; cvt.u32.u64 %0, t; }" : "=r"(a) : "l"(p));
    return a;
}
#define CP_ASYNC16(dst, src) \
    asm volatile("cp.async.cg.shared.global [%0], [%1], 16;" :: "r"(dst), "l"(src))
#define CP_COMMIT() asm volatile("cp.async.commit_group;" ::: "memory")
#define CP_WAIT(n)  asm volatile("cp.async.wait_group %0;" :: "n"(n) : "memory")

#define LDSM_X4(r0, r1, r2, r3, addr) \
    asm volatile("ldmatrix.sync.aligned.m8n8.x4.shared.b16 {%0,%1,%2,%3}, [%4];" \
                 : "=r"(r0), "=r"(r1), "=r"(r2), "=r"(r3) : "r"(addr))

#define MMA_BF16(c, a, b) \
    asm volatile("mma.sync.aligned.m16n8k16.row.col.f32.bf16.bf16.f32 " \
                 "{%0,%1,%2,%3}, {%4,%5,%6,%7}, {%8,%9}, {%0,%1,%2,%3};" \
                 : "+f"((c)[0]), "+f"((c)[1]), "+f"((c)[2]), "+f"((c)[3]) \
                 : "r"((a)[0]), "r"((a)[1]), "r"((a)[2]), "r"((a)[3]), \
                   "r"((b)[0]), "r"((b)[1]))

__device__ __forceinline__ uint32_t sw128(uint32_t off) { return off ^ ((off >> 3) & 0x70); }

// ---------------------------------------------------------------------------
// Scratch (device globals)
// ---------------------------------------------------------------------------
__device__ float g_Q[B_ * H_ * S_ * DK_];      // [B,H,S,64]
__device__ float g_K[B_ * H_ * S_ * DK_];
__device__ float g_V[B_ * H_ * S_ * DK_];
__device__ float g_attn[(size_t)M_ * DM_];     // [B,S,1024]
__device__ __nv_bfloat16 g_Ahi[(size_t)M_ * DM_];
__device__ __nv_bfloat16 g_Alo[(size_t)M_ * DM_];
__device__ __nv_bfloat16 g_Whi[(size_t)DM_ * DM_];   // transposed: [N,K], K contiguous
__device__ __nv_bfloat16 g_Wlo[(size_t)DM_ * DM_];

// ---------------------------------------------------------------------------
// fp32 -> (hi, lo) bf16 split, same layout
// ---------------------------------------------------------------------------
__global__ void __launch_bounds__(256) conv_split(const float4* __restrict__ src,
                                                  __nv_bfloat162* __restrict__ hi,
                                                  __nv_bfloat162* __restrict__ lo, int n4)
{
    int i = blockIdx.x * 256 + threadIdx.x;
    if (i >= n4) return;
    float4 v = src[i];
    __nv_bfloat16 hx = __float2bfloat16(v.x), hy = __float2bfloat16(v.y);
    __nv_bfloat16 hz = __float2bfloat16(v.z), hw = __float2bfloat16(v.w);
    hi[2 * i + 0] = __halves2bfloat162(hx, hy);
    hi[2 * i + 1] = __halves2bfloat162(hz, hw);
    lo[2 * i + 0] = __halves2bfloat162(__float2bfloat16(v.x - __bfloat162float(hx)),
                                       __float2bfloat16(v.y - __bfloat162float(hy)));
    lo[2 * i + 1] = __halves2bfloat162(__float2bfloat16(v.z - __bfloat162float(hz)),
                                       __float2bfloat16(v.w - __bfloat162float(hw)));
}

// ---------------------------------------------------------------------------
// W [K,N] row-major fp32 -> transposed split bf16 Wt[N,K] (K contiguous)
// ---------------------------------------------------------------------------
__global__ void __launch_bounds__(256) conv_WT(const float* __restrict__ W,
                                               __nv_bfloat16* __restrict__ hi,
                                               __nv_bfloat16* __restrict__ lo)
{
    __shared__ float tile[32][33];
    const int bx = blockIdx.x, by = blockIdx.y;
    const int tx = threadIdx.x, ty = threadIdx.y;     // 32 x 8
    #pragma unroll
    for (int j = 0; j < 32; j += 8)
        tile[ty + j][tx] = W[(size_t)(by * 32 + ty + j) * DM_ + bx * 32 + tx];
    __syncthreads();
    #pragma unroll
    for (int j = 0; j < 32; j += 8) {
        float v = tile[tx][ty + j];
        __nv_bfloat16 h = __float2bfloat16(v);
        size_t o = (size_t)(bx * 32 + ty + j) * DM_ + by * 32 + tx;
        hi[o] = h;
        lo[o] = __float2bfloat16(v - __bfloat162float(h));
    }
}

// ---------------------------------------------------------------------------
// HMMA GEMM: C[4096,1024] = A @ W + bias via 3 bf16 passes
//   seg0: Ahi*Whi, seg1: Alo*Whi, seg2: Ahi*Wlo  (virtual K = 3*1024)
// CTA tile 128x128, BK=64, cp.async double buffer, 8 warps (4Mx2N),
// warp tile 32x64 = 2x8 m16n8k16 MMAs per k-step.
// mode 0/1/2 -> head-split write to g_Q/g_K/g_V; mode 3 -> Cext [M,1024].
// ---------------------------------------------------------------------------
#define GM 128
#define GN 128
#define NCH 48
#define GEMM_SMEM (4 * 16384)

__global__ void __launch_bounds__(256) gemm_mma(const float* __restrict__ bias,
                                                float* __restrict__ Cext, int mode)
{
    extern __shared__ __align__(1024) char smem[];
    const uint32_t sb = smem_u32(smem);
    const int t = threadIdx.x, lane = t & 31, wid = t >> 5;
    const int warpM = wid >> 1, warpN = wid & 1;
    const int row0 = blockIdx.y * GM, col0 = blockIdx.x * GN;

    float c[2][8][4] = {};

    // per-thread load coords (4 x 16B for A, 4 x 16B for B)
    int lr[4], lc[4];
    #pragma unroll
    for (int j = 0; j < 4; j++) {
        int g = t + j * 256;
        lr[j] = g >> 3;
        lc[j] = (g & 7) * 8;
    }

    auto issue = [&](int i) {
        const int seg = i >> 4, kc = (i & 15) * 64;
        const __nv_bfloat16* aseg = (seg == 1) ? g_Alo : g_Ahi;
        const __nv_bfloat16* wseg = (seg == 2) ? g_Wlo : g_Whi;
        const uint32_t ab = sb + (uint32_t)(i & 1) * 32768u;
        const uint32_t bb = ab + 16384u;
        #pragma unroll
        for (int j = 0; j < 4; j++) {
            uint32_t so = sw128((uint32_t)(lr[j] * 128 + lc[j] * 2));
            CP_ASYNC16(ab + so, aseg + (size_t)(row0 + lr[j]) * DM_ + kc + lc[j]);
            CP_ASYNC16(bb + so, wseg + (size_t)(col0 + lr[j]) * DM_ + kc + lc[j]);
        }
    };

    issue(0);
    CP_COMMIT();

    for (int i = 0; i < NCH; i++) {
        if (i + 1 < NCH) { issue(i + 1); CP_COMMIT(); CP_WAIT(1); }
        else             { CP_WAIT(0); }
        __syncthreads();

        const uint32_t ab = sb + (uint32_t)(i & 1) * 32768u;
        const uint32_t bb = ab + 16384u;

        #pragma unroll
        for (int kst = 0; kst < 4; kst++) {
            const int kk = kst * 16;
            uint32_t a[2][4], b[8][2];
            #pragma unroll
            for (int mt = 0; mt < 2; mt++) {
                int r = warpM * 32 + mt * 16 + (lane & 7) + ((lane >> 3) & 1) * 8;
                int kcol = kk + (lane >> 4) * 8;
                LDSM_X4(a[mt][0], a[mt][1], a[mt][2], a[mt][3],
                        ab + sw128((uint32_t)(r * 128 + kcol * 2)));
            }
            #pragma unroll
            for (int np = 0; np < 4; np++) {
                int r = warpN * 64 + np * 16 + (lane & 7) + (lane >> 4) * 8;
                int kcol = kk + ((lane >> 3) & 1) * 8;
                LDSM_X4(b[2 * np][0], b[2 * np][1], b[2 * np + 1][0], b[2 * np + 1][1],
                        bb + sw128((uint32_t)(r * 128 + kcol * 2)));
            }
            #pragma unroll
            for (int mt = 0; mt < 2; mt++)
                #pragma unroll
                for (int nt = 0; nt < 8; nt++)
                    MMA_BF16(c[mt][nt], a[mt], b[nt]);
        }
        __syncthreads();
    }

    // Epilogue: c frag thread map: rows lane>>2 (+8), cols (lane&3)*2 (+1)
    float* Cb = (mode == 0) ? g_Q : (mode == 1) ? g_K : (mode == 2) ? g_V : Cext;
    #pragma unroll
    for (int mt = 0; mt < 2; mt++) {
        #pragma unroll
        for (int half = 0; half < 2; half++) {
            const int rowg = row0 + warpM * 32 + mt * 16 + (lane >> 2) + half * 8;
            const int bb_ = rowg >> 11, ss = rowg & (S_ - 1);
            #pragma unroll
            for (int nt = 0; nt < 8; nt++) {
                const int colg = col0 + warpN * 64 + nt * 8 + (lane & 3) * 2;
                const float v0 = c[mt][nt][half * 2 + 0] + bias[colg];
                const float v1 = c[mt][nt][half * 2 + 1] + bias[colg + 1];
                float* dst;
                if (mode < 3) {
                    const int h = colg >> 6;
                    dst = Cb + ((size_t)((bb_ * H_ + h) * S_ + ss)) * DK_ + (colg & 63);
                } else {
                    dst = Cb + (size_t)rowg * DM_ + colg;
                }
                *reinterpret_cast<float2*>(dst) = make_float2(v0, v1);
            }
        }
    }
}

// ----------------------------------------------------------------------------
// Flash attention, causal (fp32, unchanged from round 1).
// ----------------------------------------------------------------------------
__global__ void __launch_bounds__(256) attn64()
{
    extern __shared__ __align__(16) float sh[];
    float* Qs = sh;
    float* Ks = Qs + 64 * 68;
    float* Vs = Ks + 64 * 68;
    float* Ps = Vs + 64 * 68;

    const int qb = blockIdx.x;
    const int bh = blockIdx.y;
    const int qs = qb * 64;
    const int t  = threadIdx.x;
    const int tx = t & 15, ty = t >> 4;

    const float* Qg = g_Q + (size_t)bh * S_ * DK_;
    const float* Kg = g_K + (size_t)bh * S_ * DK_;
    const float* Vg = g_V + (size_t)bh * S_ * DK_;

    {
        const int d4 = (t & 15) << 2;
        const int r0 = t >> 4;
        #pragma unroll
        for (int rep = 0; rep < 4; rep++) {
            int r = r0 + rep * 16;
            float4 v = *reinterpret_cast<const float4*>(Qg + (size_t)(qs + r) * DK_ + d4);
            Qs[(d4 + 0) * 68 + r] = v.x;
            Qs[(d4 + 1) * 68 + r] = v.y;
            Qs[(d4 + 2) * 68 + r] = v.z;
            Qs[(d4 + 3) * 68 + r] = v.w;
        }
    }

    float o[4][4] = {};
    float m[4], l[4];
    #pragma unroll
    for (int i = 0; i < 4; i++) { m[i] = -INFINITY; l[i] = 0.f; }

    for (int kt = 0; kt <= qs; kt += 64) {
        __syncthreads();
        {
            const int d4 = (t & 15) << 2;
            const int r0 = t >> 4;
            #pragma unroll
            for (int rep = 0; rep < 4; rep++) {
                int r = r0 + rep * 16;
                float4 kv = *reinterpret_cast<const float4*>(Kg + (size_t)(kt + r) * DK_ + d4);
                Ks[(d4 + 0) * 68 + r] = kv.x;
                Ks[(d4 + 1) * 68 + r] = kv.y;
                Ks[(d4 + 2) * 68 + r] = kv.z;
                Ks[(d4 + 3) * 68 + r] = kv.w;
                float4 vv = *reinterpret_cast<const float4*>(Vg + (size_t)(kt + r) * DK_ + d4);
                *reinterpret_cast<float4*>(&Vs[r * 68 + d4]) = vv;
            }
        }
        __syncthreads();

        float s[4][4] = {};
        #pragma unroll 8
        for (int d = 0; d < 64; d++) {
            float4 a = *reinterpret_cast<const float4*>(&Qs[d * 68 + (ty << 2)]);
            float4 b = *reinterpret_cast<const float4*>(&Ks[d * 68 + (tx << 2)]);
            float av[4] = {a.x, a.y, a.z, a.w};
            float bv[4] = {b.x, b.y, b.z, b.w};
            #pragma unroll
            for (int i = 0; i < 4; i++)
                #pragma unroll
                for (int j = 0; j < 4; j++)
                    s[i][j] = fmaf(av[i], bv[j], s[i][j]);
        }

        const bool diag = (kt == qs);
        #pragma unroll
        for (int i = 0; i < 4; i++) {
            int r = (ty << 2) + i;
            #pragma unroll
            for (int j = 0; j < 4; j++) {
                int cc = (tx << 2) + j;
                float val = s[i][j] * 0.125f;
                if (diag && cc > r) val = -INFINITY;
                s[i][j] = val;
            }
            float mx = fmaxf(fmaxf(s[i][0], s[i][1]), fmaxf(s[i][2], s[i][3]));
            #pragma unroll
            for (int off = 8; off; off >>= 1)
                mx = fmaxf(mx, __shfl_xor_sync(0xffffffffu, mx, off));
            float mnew  = fmaxf(m[i], mx);
            float alpha = __expf(m[i] - mnew);
            float rs = 0.f;
            #pragma unroll
            for (int j = 0; j < 4; j++) {
                float p = __expf(s[i][j] - mnew);
                s[i][j] = p;
                rs += p;
            }
            #pragma unroll
            for (int off = 8; off; off >>= 1)
                rs += __shfl_xor_sync(0xffffffffu, rs, off);
            l[i] = l[i] * alpha + rs;
            m[i] = mnew;
            #pragma unroll
            for (int j = 0; j < 4; j++) o[i][j] *= alpha;
            #pragma unroll
            for (int j = 0; j < 4; j++)
                Ps[((tx << 2) + j) * 68 + (ty << 2) + i] = s[i][j];
        }
        __syncthreads();

        #pragma unroll 8
        for (int k = 0; k < 64; k++) {
            float4 a = *reinterpret_cast<const float4*>(&Ps[k * 68 + (ty << 2)]);
            float4 b = *reinterpret_cast<const float4*>(&Vs[k * 68 + (tx << 2)]);
            float av[4] = {a.x, a.y, a.z, a.w};
            float bv[4] = {b.x, b.y, b.z, b.w};
            #pragma unroll
            for (int i = 0; i < 4; i++)
                #pragma unroll
                for (int j = 0; j < 4; j++)
                    o[i][j] = fmaf(av[i], bv[j], o[i][j]);
        }
    }

    const int b = bh >> 4, h = bh & 15;
    #pragma unroll
    for (int i = 0; i < 4; i++) {
        float inv = 1.0f / l[i];
        int row = qs + (ty << 2) + i;
        float4 v = make_float4(o[i][0] * inv, o[i][1] * inv, o[i][2] * inv, o[i][3] * inv);
        *reinterpret_cast<float4*>(g_attn + ((size_t)(b * S_ + row)) * DM_ + h * DK_ + (tx << 2)) = v;
    }
}

// ----------------------------------------------------------------------------
extern "C" void kernel_launch(void* const* d_in, const int* in_sizes, int n_in,
                              void* d_out, int out_size)
{
    const float* query = (const float*)d_in[0];
    const float* key   = (const float*)d_in[1];
    const float* value = (const float*)d_in[2];
    const float* Wq = (const float*)d_in[4];
    const float* bq = (const float*)d_in[5];
    const float* Wk = (const float*)d_in[6];
    const float* bk = (const float*)d_in[7];
    const float* Wv = (const float*)d_in[8];
    const float* bv = (const float*)d_in[9];
    const float* Wo = (const float*)d_in[10];
    const float* bo = (const float*)d_in[11];
    float* out = (float*)d_out;

    const int attn_smem = 4 * 64 * 68 * (int)sizeof(float);
    cudaFuncSetAttribute(attn64, cudaFuncAttributeMaxDynamicSharedMemorySize, attn_smem);
    cudaFuncSetAttribute(gemm_mma, cudaFuncAttributeMaxDynamicSharedMemorySize, GEMM_SMEM);

    const int n4 = M_ * DM_ / 4;
    const dim3 cvb(256), cvg(n4 / 256);
    const dim3 wtg(32, 32), wtb(32, 8);
    const dim3 gg(DM_ / GN, M_ / GM);

    float* g_attn_ptr = nullptr;
    cudaGetSymbolAddress((void**)&g_attn_ptr, g_attn);

    __nv_bfloat162* Ahi2; __nv_bfloat162* Alo2;
    cudaGetSymbolAddress((void**)&Ahi2, g_Ahi);
    cudaGetSymbolAddress((void**)&Alo2, g_Alo);
    __nv_bfloat16* Whi; __nv_bfloat16* Wlo;
    cudaGetSymbolAddress((void**)&Whi, g_Whi);
    cudaGetSymbolAddress((void**)&Wlo, g_Wlo);

    // Q projection
    conv_split<<<cvg, cvb>>>((const float4*)query, Ahi2, Alo2, n4);
    conv_WT<<<wtg, wtb>>>(Wq, Whi, Wlo);
    gemm_mma<<<gg, 256, GEMM_SMEM>>>(bq, nullptr, 0);
    // K projection
    conv_split<<<cvg, cvb>>>((const float4*)key, Ahi2, Alo2, n4);
    conv_WT<<<wtg, wtb>>>(Wk, Whi, Wlo);
    gemm_mma<<<gg, 256, GEMM_SMEM>>>(bk, nullptr, 1);
    // V projection
    conv_split<<<cvg, cvb>>>((const float4*)value, Ahi2, Alo2, n4);
    conv_WT<<<wtg, wtb>>>(Wv, Whi, Wlo);
    gemm_mma<<<gg, 256, GEMM_SMEM>>>(bv, nullptr, 2);
    // Attention
    attn64<<<dim3(S_ / 64, B_ * H_), 256, attn_smem>>>();
    // Output projection
    conv_split<<<cvg, cvb>>>((const float4*)g_attn_ptr, Ahi2, Alo2, n4);
    conv_WT<<<wtg, wtb>>>(Wo, Whi, Wlo);
    gemm_mma<<<gg, 256, GEMM_SMEM>>>(bo, out, 3);
}

// round 4
// speedup vs baseline: 3.2640x; 1.9162x over previous
#include <cuda_runtime.h>
#include <cuda_bf16.h>
#include <math.h>
#include <cstdint>

#define B_   2
#define S_   2048
#define H_   16
#define DK_  64
#define DM_  1024
#define M_   (B_ * S_)   // 4096

// ---------------------------------------------------------------------------
// PTX helpers — sm_80+ portable (harness PTX target is sm_103 WITHOUT 'a';
// tcgen05/TMEM unavailable; mma.sync/ldmatrix/cp.async are the path).
// ---------------------------------------------------------------------------
__device__ __forceinline__ uint32_t smem_u32(const void* p) {
    uint32_t a;
    asm("{ .reg .u64 t; cvta.to.shared.u64 t, %1; cvt.u32.u64 %0, t; }" : "=r"(a) : "l"(p));
    return a;
}
#define CP_ASYNC16(dst, src) \
    asm volatile("cp.async.cg.shared.global [%0], [%1], 16;" :: "r"(dst), "l"(src))
#define CP_COMMIT() asm volatile("cp.async.commit_group;" ::: "memory")
#define CP_WAIT(n)  asm volatile("cp.async.wait_group %0;" :: "n"(n) : "memory")

#define LDSM_X4(r0, r1, r2, r3, addr) \
    asm volatile("ldmatrix.sync.aligned.m8n8.x4.shared.b16 {%0,%1,%2,%3}, [%4];" \
                 : "=r"(r0), "=r"(r1), "=r"(r2), "=r"(r3) : "r"(addr))

#define MMA_BF16(c, a, b) \
    asm volatile("mma.sync.aligned.m16n8k16.row.col.f32.bf16.bf16.f32 " \
                 "{%0,%1,%2,%3}, {%4,%5,%6,%7}, {%8,%9}, {%0,%1,%2,%3};" \
                 : "+f"((c)[0]), "+f"((c)[1]), "+f"((c)[2]), "+f"((c)[3]) \
                 : "r"((a)[0]), "r"((a)[1]), "r"((a)[2]), "r"((a)[3]), \
                   "r"((b)[0]), "r"((b)[1]))

__device__ __forceinline__ uint32_t sw128(uint32_t off) { return off ^ ((off >> 3) & 0x70); }

// split (x, y) fp32 -> packed bf16x2 hi + lo (residual)
__device__ __forceinline__ void split2(float x, float y, uint32_t& hi, uint32_t& lo) {
    __nv_bfloat16 hx = __float2bfloat16(x), hy = __float2bfloat16(y);
    __nv_bfloat162 h2 = __halves2bfloat162(hx, hy);
    __nv_bfloat162 l2 = __halves2bfloat162(__float2bfloat16(x - __bfloat162float(hx)),
                                           __float2bfloat16(y - __bfloat162float(hy)));
    hi = *reinterpret_cast<uint32_t*>(&h2);
    lo = *reinterpret_cast<uint32_t*>(&l2);
}

// ---------------------------------------------------------------------------
// Scratch (device globals)
// ---------------------------------------------------------------------------
__device__ __nv_bfloat16 g_Ahi[(size_t)M_ * DM_];    // GEMM A operand hi / attn out hi
__device__ __nv_bfloat16 g_Alo[(size_t)M_ * DM_];
__device__ __nv_bfloat16 g_Whi[(size_t)DM_ * DM_];   // W^T [N,K] K-contig
__device__ __nv_bfloat16 g_Wlo[(size_t)DM_ * DM_];
__device__ __nv_bfloat16 g_Qhi[B_ * H_ * S_ * DK_];  // [B,H,S,64]
__device__ __nv_bfloat16 g_Qlo[B_ * H_ * S_ * DK_];
__device__ __nv_bfloat16 g_Khi[B_ * H_ * S_ * DK_];
__device__ __nv_bfloat16 g_Klo[B_ * H_ * S_ * DK_];
__device__ __nv_bfloat16 g_Vhi[B_ * H_ * S_ * DK_];
__device__ __nv_bfloat16 g_Vlo[B_ * H_ * S_ * DK_];
__device__ __nv_bfloat16 g_Vthi[B_ * H_ * DK_ * S_]; // [B,H,64,S] (V^T)
__device__ __nv_bfloat16 g_Vtlo[B_ * H_ * DK_ * S_];

// ---------------------------------------------------------------------------
// fp32 -> (hi, lo) bf16 split
// ---------------------------------------------------------------------------
__global__ void __launch_bounds__(256) conv_split(const float4* __restrict__ src,
                                                  __nv_bfloat162* __restrict__ hi,
                                                  __nv_bfloat162* __restrict__ lo, int n4)
{
    int i = blockIdx.x * 256 + threadIdx.x;
    if (i >= n4) return;
    float4 v = src[i];
    uint32_t h0, l0, h1, l1;
    split2(v.x, v.y, h0, l0);
    split2(v.z, v.w, h1, l1);
    reinterpret_cast<uint32_t*>(hi)[2 * i + 0] = h0;
    reinterpret_cast<uint32_t*>(hi)[2 * i + 1] = h1;
    reinterpret_cast<uint32_t*>(lo)[2 * i + 0] = l0;
    reinterpret_cast<uint32_t*>(lo)[2 * i + 1] = l1;
}

// ---------------------------------------------------------------------------
// W [K,N] row-major fp32 -> transposed split bf16 Wt[N,K]
// ---------------------------------------------------------------------------
__global__ void __launch_bounds__(256) conv_WT(const float* __restrict__ W,
                                               __nv_bfloat16* __restrict__ hi,
                                               __nv_bfloat16* __restrict__ lo)
{
    __shared__ float tile[32][33];
    const int bx = blockIdx.x, by = blockIdx.y;
    const int tx = threadIdx.x, ty = threadIdx.y;     // 32 x 8
    #pragma unroll
    for (int j = 0; j < 32; j += 8)
        tile[ty + j][tx] = W[(size_t)(by * 32 + ty + j) * DM_ + bx * 32 + tx];
    __syncthreads();
    #pragma unroll
    for (int j = 0; j < 32; j += 8) {
        float v = tile[tx][ty + j];
        __nv_bfloat16 h = __float2bfloat16(v);
        size_t o = (size_t)(bx * 32 + ty + j) * DM_ + by * 32 + tx;
        hi[o] = h;
        lo[o] = __float2bfloat16(v - __bfloat162float(h));
    }
}

// ---------------------------------------------------------------------------
// V [B,H,S,64] hi/lo -> V^T [B,H,64,S] hi/lo
// ---------------------------------------------------------------------------
__global__ void __launch_bounds__(256) transpV()
{
    __shared__ __nv_bfloat16 th[64][65], tl[64][65];
    const int s0 = blockIdx.x * 64, bh = blockIdx.y;
    const int t = threadIdx.x;
    const __nv_bfloat16* sh_ = g_Vhi + (size_t)bh * S_ * DK_;
    const __nv_bfloat16* sl_ = g_Vlo + (size_t)bh * S_ * DK_;
    #pragma unroll
    for (int it = 0; it < 2; it++) {
        int r = (t >> 3) + it * 32, c = (t & 7) * 8;
        #pragma unroll
        for (int q = 0; q < 8; q++) {
            th[r][c + q] = sh_[(size_t)(s0 + r) * DK_ + c + q];
            tl[r][c + q] = sl_[(size_t)(s0 + r) * DK_ + c + q];
        }
    }
    __syncthreads();
    __nv_bfloat16* dh = g_Vthi + (size_t)bh * DK_ * S_;
    __nv_bfloat16* dl = g_Vtlo + (size_t)bh * DK_ * S_;
    #pragma unroll
    for (int it = 0; it < 2; it++) {
        int d = (t >> 3) + it * 32, sc = (t & 7) * 8;
        #pragma unroll
        for (int q = 0; q < 8; q++) {
            dh[(size_t)d * S_ + s0 + sc + q] = th[sc + q][d];
            dl[(size_t)d * S_ + s0 + sc + q] = tl[sc + q][d];
        }
    }
}

// ---------------------------------------------------------------------------
// HMMA GEMM: C[4096,1024] = A @ W + bias via 3 bf16 passes.
// modes 0/1/2 -> head-split bf16 hi/lo into Q/K/V buffers; mode 3 -> fp32 Cext.
// ---------------------------------------------------------------------------
#define GM 128
#define GN 128
#define NCH 48
#define GEMM_SMEM (4 * 16384)

__global__ void __launch_bounds__(256) gemm_mma(const float* __restrict__ bias,
                                                float* __restrict__ Cext, int mode)
{
    extern __shared__ __align__(1024) char smem[];
    const uint32_t sb = smem_u32(smem);
    const int t = threadIdx.x, lane = t & 31, wid = t >> 5;
    const int warpM = wid >> 1, warpN = wid & 1;
    const int row0 = blockIdx.y * GM, col0 = blockIdx.x * GN;

    float c[2][8][4] = {};

    int lr[4], lc[4];
    #pragma unroll
    for (int j = 0; j < 4; j++) {
        int g = t + j * 256;
        lr[j] = g >> 3;
        lc[j] = (g & 7) * 8;
    }

    auto issue = [&](int i) {
        const int seg = i >> 4, kc = (i & 15) * 64;
        const __nv_bfloat16* aseg = (seg == 1) ? g_Alo : g_Ahi;
        const __nv_bfloat16* wseg = (seg == 2) ? g_Wlo : g_Whi;
        const uint32_t ab = sb + (uint32_t)(i & 1) * 32768u;
        const uint32_t bb = ab + 16384u;
        #pragma unroll
        for (int j = 0; j < 4; j++) {
            uint32_t so = sw128((uint32_t)(lr[j] * 128 + lc[j] * 2));
            CP_ASYNC16(ab + so, aseg + (size_t)(row0 + lr[j]) * DM_ + kc + lc[j]);
            CP_ASYNC16(bb + so, wseg + (size_t)(col0 + lr[j]) * DM_ + kc + lc[j]);
        }
    };

    issue(0);
    CP_COMMIT();

    for (int i = 0; i < NCH; i++) {
        if (i + 1 < NCH) { issue(i + 1); CP_COMMIT(); CP_WAIT(1); }
        else             { CP_WAIT(0); }
        __syncthreads();

        const uint32_t ab = sb + (uint32_t)(i & 1) * 32768u;
        const uint32_t bb = ab + 16384u;

        #pragma unroll
        for (int kst = 0; kst < 4; kst++) {
            const int kk = kst * 16;
            uint32_t a[2][4], b[8][2];
            #pragma unroll
            for (int mt = 0; mt < 2; mt++) {
                int r = warpM * 32 + mt * 16 + (lane & 7) + ((lane >> 3) & 1) * 8;
                int kcol = kk + (lane >> 4) * 8;
                LDSM_X4(a[mt][0], a[mt][1], a[mt][2], a[mt][3],
                        ab + sw128((uint32_t)(r * 128 + kcol * 2)));
            }
            #pragma unroll
            for (int np = 0; np < 4; np++) {
                int r = warpN * 64 + np * 16 + (lane & 7) + (lane >> 4) * 8;
                int kcol = kk + ((lane >> 3) & 1) * 8;
                LDSM_X4(b[2 * np][0], b[2 * np][1], b[2 * np + 1][0], b[2 * np + 1][1],
                        bb + sw128((uint32_t)(r * 128 + kcol * 2)));
            }
            #pragma unroll
            for (int mt = 0; mt < 2; mt++)
                #pragma unroll
                for (int nt = 0; nt < 8; nt++)
                    MMA_BF16(c[mt][nt], a[mt], b[nt]);
        }
        __syncthreads();
    }

    __nv_bfloat16* Hb = (mode == 0) ? g_Qhi : (mode == 1) ? g_Khi : g_Vhi;
    __nv_bfloat16* Lb = (mode == 0) ? g_Qlo : (mode == 1) ? g_Klo : g_Vlo;
    #pragma unroll
    for (int mt = 0; mt < 2; mt++) {
        #pragma unroll
        for (int half = 0; half < 2; half++) {
            const int rowg = row0 + warpM * 32 + mt * 16 + (lane >> 2) + half * 8;
            const int bb_ = rowg >> 11, ss = rowg & (S_ - 1);
            #pragma unroll
            for (int nt = 0; nt < 8; nt++) {
                const int colg = col0 + warpN * 64 + nt * 8 + (lane & 3) * 2;
                const float v0 = c[mt][nt][half * 2 + 0] + bias[colg];
                const float v1 = c[mt][nt][half * 2 + 1] + bias[colg + 1];
                if (mode < 3) {
                    const int h = colg >> 6;
                    size_t off = ((size_t)((bb_ * H_ + h) * S_ + ss)) * DK_ + (colg & 63);
                    uint32_t hiw, low;
                    split2(v0, v1, hiw, low);
                    *reinterpret_cast<uint32_t*>(Hb + off) = hiw;
                    *reinterpret_cast<uint32_t*>(Lb + off) = low;
                } else {
                    *reinterpret_cast<float2*>(Cext + (size_t)rowg * DM_ + colg) =
                        make_float2(v0, v1);
                }
            }
        }
    }
}

// ---------------------------------------------------------------------------
// HMMA flash attention, causal, hi/lo split on QK^T and PV.
// CTA = 128 query rows of one (b,h); 8 warps x 16 rows; 64 keys / iteration.
// Output: bf16 hi/lo into g_Ahi/g_Alo at [B,S,1024] (A operand of out-proj).
// ---------------------------------------------------------------------------
#define ATT_SMEM 98304

__global__ void __launch_bounds__(256, 1) attn_mma()
{
    extern __shared__ __align__(1024) char smem[];
    const uint32_t sb = smem_u32(smem);
    const int t = threadIdx.x, lane = t & 31, w = t >> 5;
    const int qb = blockIdx.x, bh = blockIdx.y;
    const int qs = qb * 128;
    const int ntiles = qb * 2 + 2;

    const size_t bo = (size_t)bh * S_ * DK_;
    const __nv_bfloat16* Qh = g_Qhi + bo;
    const __nv_bfloat16* Ql = g_Qlo + bo;
    const __nv_bfloat16* Kh = g_Khi + bo;
    const __nv_bfloat16* Kl = g_Klo + bo;
    const __nv_bfloat16* Vh = g_Vthi + (size_t)bh * DK_ * S_;
    const __nv_bfloat16* Vl = g_Vtlo + (size_t)bh * DK_ * S_;

    const uint32_t QH = sb, QL = sb + 16384;

    // Q tiles (128x64 hi + lo), grouped with KV tile 0
    #pragma unroll
    for (int j = 0; j < 4; j++) {
        int g = t + j * 256, r = g >> 3, c = (g & 7) * 8;
        uint32_t so = sw128((uint32_t)(r * 128 + c * 2));
        CP_ASYNC16(QH + so, Qh + (size_t)(qs + r) * DK_ + c);
        CP_ASYNC16(QL + so, Ql + (size_t)(qs + r) * DK_ + c);
    }
    auto issueKV = [&](int i) {
        const int kt = i * 64;
        const uint32_t bB = sb + 32768u + (uint32_t)(i & 1) * 32768u;
        #pragma unroll
        for (int j = 0; j < 2; j++) {
            int g = t + j * 256, r = g >> 3, c = (g & 7) * 8;
            uint32_t so = sw128((uint32_t)(r * 128 + c * 2));
            CP_ASYNC16(bB + so,         Kh + (size_t)(kt + r) * DK_ + c);
            CP_ASYNC16(bB + 8192 + so,  Kl + (size_t)(kt + r) * DK_ + c);
            CP_ASYNC16(bB + 16384 + so, Vh + (size_t)r * S_ + kt + c);
            CP_ASYNC16(bB + 24576 + so, Vl + (size_t)r * S_ + kt + c);
        }
    };
    issueKV(0);
    CP_COMMIT();
    if (ntiles > 1) { issueKV(1); CP_COMMIT(); }

    uint32_t qhf[4][4], qlf[4][4];
    float o[8][4] = {};
    float mrow0 = -INFINITY, mrow1 = -INFINITY, lrow0 = 0.f, lrow1 = 0.f;

    for (int i = 0; i < ntiles; i++) {
        if (i + 1 < ntiles) CP_WAIT(1); else CP_WAIT(0);
        __syncthreads();

        if (i == 0) {  // extract Q fragments to registers (group 0 complete)
            #pragma unroll
            for (int kc = 0; kc < 4; kc++) {
                int r = w * 16 + (lane & 7) + ((lane >> 3) & 1) * 8;
                int kcol = kc * 16 + (lane >> 4) * 8;
                uint32_t so = sw128((uint32_t)(r * 128 + kcol * 2));
                LDSM_X4(qhf[kc][0], qhf[kc][1], qhf[kc][2], qhf[kc][3], QH + so);
                LDSM_X4(qlf[kc][0], qlf[kc][1], qlf[kc][2], qlf[kc][3], QL + so);
            }
        }

        const int kt = i * 64;
        const uint32_t bB = sb + 32768u + (uint32_t)(i & 1) * 32768u;

        // ---- S = Qhi*Khi + Qlo*Khi + Qhi*Klo   (m16 x n64 x k64 per warp)
        float s[8][4] = {};
        #pragma unroll
        for (int kc = 0; kc < 4; kc++) {
            const int kk = kc * 16;
            uint32_t bf[8][2];
            #pragma unroll
            for (int np = 0; np < 4; np++) {
                int r = np * 16 + (lane & 7) + (lane >> 4) * 8;
                int kcol = kk + ((lane >> 3) & 1) * 8;
                LDSM_X4(bf[2 * np][0], bf[2 * np][1], bf[2 * np + 1][0], bf[2 * np + 1][1],
                        bB + sw128((uint32_t)(r * 128 + kcol * 2)));
            }
            #pragma unroll
            for (int j = 0; j < 8; j++) {
                MMA_BF16(s[j], qhf[kc], bf[j]);
                MMA_BF16(s[j], qlf[kc], bf[j]);
            }
            #pragma unroll
            for (int np = 0; np < 4; np++) {
                int r = np * 16 + (lane & 7) + (lane >> 4) * 8;
                int kcol = kk + ((lane >> 3) & 1) * 8;
                LDSM_X4(bf[2 * np][0], bf[2 * np][1], bf[2 * np + 1][0], bf[2 * np + 1][1],
                        bB + 8192 + sw128((uint32_t)(r * 128 + kcol * 2)));
            }
            #pragma unroll
            for (int j = 0; j < 8; j++)
                MMA_BF16(s[j], qhf[kc], bf[j]);
        }

        // ---- scale + causal mask + online softmax
        const int r0g = qs + w * 16 + (lane >> 2);
        const bool needmask = (kt + 63 > qs + w * 16);
        float mx0 = -INFINITY, mx1 = -INFINITY;
        #pragma unroll
        for (int j = 0; j < 8; j++) {
            const int cg = kt + j * 8 + (lane & 3) * 2;
            float v0 = s[j][0] * 0.125f, v1 = s[j][1] * 0.125f;
            float v2 = s[j][2] * 0.125f, v3 = s[j][3] * 0.125f;
            if (needmask) {
                if (cg     > r0g)     v0 = -INFINITY;
                if (cg + 1 > r0g)     v1 = -INFINITY;
                if (cg     > r0g + 8) v2 = -INFINITY;
                if (cg + 1 > r0g + 8) v3 = -INFINITY;
            }
            s[j][0] = v0; s[j][1] = v1; s[j][2] = v2; s[j][3] = v3;
            mx0 = fmaxf(mx0, fmaxf(v0, v1));
            mx1 = fmaxf(mx1, fmaxf(v2, v3));
        }
        mx0 = fmaxf(mx0, __shfl_xor_sync(0xffffffffu, mx0, 1));
        mx0 = fmaxf(mx0, __shfl_xor_sync(0xffffffffu, mx0, 2));
        mx1 = fmaxf(mx1, __shfl_xor_sync(0xffffffffu, mx1, 1));
        mx1 = fmaxf(mx1, __shfl_xor_sync(0xffffffffu, mx1, 2));
        const float mn0 = fmaxf(mrow0, mx0), mn1 = fmaxf(mrow1, mx1);
        const float al0 = __expf(mrow0 - mn0), al1 = __expf(mrow1 - mn1);
        float sum0 = 0.f, sum1 = 0.f;
        #pragma unroll
        for (int j = 0; j < 8; j++) {
            float p0 = __expf(s[j][0] - mn0); s[j][0] = p0; sum0 += p0;
            float p1 = __expf(s[j][1] - mn0); s[j][1] = p1; sum0 += p1;
            float p2 = __expf(s[j][2] - mn1); s[j][2] = p2; sum1 += p2;
            float p3 = __expf(s[j][3] - mn1); s[j][3] = p3; sum1 += p3;
        }
        sum0 += __shfl_xor_sync(0xffffffffu, sum0, 1);
        sum0 += __shfl_xor_sync(0xffffffffu, sum0, 2);
        sum1 += __shfl_xor_sync(0xffffffffu, sum1, 1);
        sum1 += __shfl_xor_sync(0xffffffffu, sum1, 2);
        lrow0 = lrow0 * al0 + sum0;
        lrow1 = lrow1 * al1 + sum1;
        mrow0 = mn0; mrow1 = mn1;
        #pragma unroll
        for (int j = 0; j < 8; j++) {
            o[j][0] *= al0; o[j][1] *= al0;
            o[j][2] *= al1; o[j][3] *= al1;
        }

        // ---- convert P fragments to bf16 hi/lo A-fragments (in-register)
        uint32_t phi[4][4], plo[4][4];
        #pragma unroll
        for (int kc = 0; kc < 4; kc++) {
            split2(s[2 * kc][0],     s[2 * kc][1],     phi[kc][0], plo[kc][0]);
            split2(s[2 * kc][2],     s[2 * kc][3],     phi[kc][1], plo[kc][1]);
            split2(s[2 * kc + 1][0], s[2 * kc + 1][1], phi[kc][2], plo[kc][2]);
            split2(s[2 * kc + 1][2], s[2 * kc + 1][3], phi[kc][3], plo[kc][3]);
        }

        // ---- O += Phi*Vhi + Plo*Vhi + Phi*Vlo   (m16 x n64(d) x k64(keys))
        #pragma unroll
        for (int kc = 0; kc < 4; kc++) {
            const int kk = kc * 16;
            uint32_t bf[8][2];
            #pragma unroll
            for (int np = 0; np < 4; np++) {
                int r = np * 16 + (lane & 7) + (lane >> 4) * 8;
                int kcol = kk + ((lane >> 3) & 1) * 8;
                LDSM_X4(bf[2 * np][0], bf[2 * np][1], bf[2 * np + 1][0], bf[2 * np + 1][1],
                        bB + 16384 + sw128((uint32_t)(r * 128 + kcol * 2)));
            }
            #pragma unroll
            for (int j = 0; j < 8; j++) {
                MMA_BF16(o[j], phi[kc], bf[j]);
                MMA_BF16(o[j], plo[kc], bf[j]);
            }
            #pragma unroll
            for (int np = 0; np < 4; np++) {
                int r = np * 16 + (lane & 7) + (lane >> 4) * 8;
                int kcol = kk + ((lane >> 3) & 1) * 8;
                LDSM_X4(bf[2 * np][0], bf[2 * np][1], bf[2 * np + 1][0], bf[2 * np + 1][1],
                        bB + 24576 + sw128((uint32_t)(r * 128 + kcol * 2)));
            }
            #pragma unroll
            for (int j = 0; j < 8; j++)
                MMA_BF16(o[j], phi[kc], bf[j]);
        }

        __syncthreads();                       // all warps done reading buffer
        if (i + 2 < ntiles) { issueKV(i + 2); CP_COMMIT(); }
    }

    // ---- epilogue: normalize and write bf16 hi/lo to [B,S,1024]
    const float inv0 = 1.0f / lrow0, inv1 = 1.0f / lrow1;
    const int b = bh >> 4, h = bh & 15;
    const int row0g = qs + w * 16 + (lane >> 2);
    #pragma unroll
    for (int j = 0; j < 8; j++) {
        const int d = j * 8 + (lane & 3) * 2;
        size_t off0 = (size_t)(b * S_ + row0g) * DM_ + h * DK_ + d;
        size_t off1 = off0 + (size_t)8 * DM_;
        uint32_t hiw, low;
        split2(o[j][0] * inv0, o[j][1] * inv0, hiw, low);
        *reinterpret_cast<uint32_t*>(g_Ahi + off0) = hiw;
        *reinterpret_cast<uint32_t*>(g_Alo + off0) = low;
        split2(o[j][2] * inv1, o[j][3] * inv1, hiw, low);
        *reinterpret_cast<uint32_t*>(g_Ahi + off1) = hiw;
        *reinterpret_cast<uint32_t*>(g_Alo + off1) = low;
    }
}

// ----------------------------------------------------------------------------
extern "C" void kernel_launch(void* const* d_in, const int* in_sizes, int n_in,
                              void* d_out, int out_size)
{
    const float* query = (const float*)d_in[0];
    const float* key   = (const float*)d_in[1];
    const float* value = (const float*)d_in[2];
    const float* Wq = (const float*)d_in[4];
    const float* bq = (const float*)d_in[5];
    const float* Wk = (const float*)d_in[6];
    const float* bk = (const float*)d_in[7];
    const float* Wv = (const float*)d_in[8];
    const float* bv = (const float*)d_in[9];
    const float* Wo = (const float*)d_in[10];
    const float* bo = (const float*)d_in[11];
    float* out = (float*)d_out;

    cudaFuncSetAttribute(gemm_mma, cudaFuncAttributeMaxDynamicSharedMemorySize, GEMM_SMEM);
    cudaFuncSetAttribute(attn_mma, cudaFuncAttributeMaxDynamicSharedMemorySize, ATT_SMEM);

    const int n4 = M_ * DM_ / 4;
    const dim3 cvb(256), cvg(n4 / 256);
    const dim3 wtg(32, 32), wtb(32, 8);
    const dim3 gg(DM_ / GN, M_ / GM);

    __nv_bfloat162* Ahi2; __nv_bfloat162* Alo2;
    cudaGetSymbolAddress((void**)&Ahi2, g_Ahi);
    cudaGetSymbolAddress((void**)&Alo2, g_Alo);
    __nv_bfloat16* Whi; __nv_bfloat16* Wlo;
    cudaGetSymbolAddress((void**)&Whi, g_Whi);
    cudaGetSymbolAddress((void**)&Wlo, g_Wlo);

    // Q projection
    conv_split<<<cvg, cvb>>>((const float4*)query, Ahi2, Alo2, n4);
    conv_WT<<<wtg, wtb>>>(Wq, Whi, Wlo);
    gemm_mma<<<gg, 256, GEMM_SMEM>>>(bq, nullptr, 0);
    // K projection
    conv_split<<<cvg, cvb>>>((const float4*)key, Ahi2, Alo2, n4);
    conv_WT<<<wtg, wtb>>>(Wk, Whi, Wlo);
    gemm_mma<<<gg, 256, GEMM_SMEM>>>(bk, nullptr, 1);
    // V projection + transpose
    conv_split<<<cvg, cvb>>>((const float4*)value, Ahi2, Alo2, n4);
    conv_WT<<<wtg, wtb>>>(Wv, Whi, Wlo);
    gemm_mma<<<gg, 256, GEMM_SMEM>>>(bv, nullptr, 2);
    transpV<<<dim3(S_ / 64, B_ * H_), 256>>>();
    // Attention (writes g_Ahi/g_Alo)
    attn_mma<<<dim3(S_ / 128, B_ * H_), 256, ATT_SMEM>>>();
    // Output projection
    conv_WT<<<wtg, wtb>>>(Wo, Whi, Wlo);
    gemm_mma<<<gg, 256, GEMM_SMEM>>>(bo, out, 3);
}

// round 5
// speedup vs baseline: 3.2905x; 1.0081x over previous
#include <cuda_runtime.h>
#include <cuda_bf16.h>
#include <math.h>
#include <cstdint>

#define B_   2
#define S_   2048
#define H_   16
#define DK_  64
#define DM_  1024
#define M_   (B_ * S_)   // 4096

// ---------------------------------------------------------------------------
// PTX helpers — sm_80+ portable (harness PTX target is sm_103 WITHOUT 'a';
// tcgen05/TMEM unavailable; mma.sync/ldmatrix/cp.async are the path).
// ---------------------------------------------------------------------------
__device__ __forceinline__ uint32_t smem_u32(const void* p) {
    uint32_t a;
    asm("{ .reg .u64 t; cvta.to.shared.u64 t, %1; cvt.u32.u64 %0, t; }" : "=r"(a) : "l"(p));
    return a;
}
#define CP_ASYNC16(dst, src) \
    asm volatile("cp.async.cg.shared.global [%0], [%1], 16;" :: "r"(dst), "l"(src))
#define CP_COMMIT() asm volatile("cp.async.commit_group;" ::: "memory")
#define CP_WAIT(n)  asm volatile("cp.async.wait_group %0;" :: "n"(n) : "memory")

#define LDSM_X4(r0, r1, r2, r3, addr) \
    asm volatile("ldmatrix.sync.aligned.m8n8.x4.shared.b16 {%0,%1,%2,%3}, [%4];" \
                 : "=r"(r0), "=r"(r1), "=r"(r2), "=r"(r3) : "r"(addr))

#define MMA_BF16(c, a, b) \
    asm volatile("mma.sync.aligned.m16n8k16.row.col.f32.bf16.bf16.f32 " \
                 "{%0,%1,%2,%3}, {%4,%5,%6,%7}, {%8,%9}, {%0,%1,%2,%3};" \
                 : "+f"((c)[0]), "+f"((c)[1]), "+f"((c)[2]), "+f"((c)[3]) \
                 : "r"((a)[0]), "r"((a)[1]), "r"((a)[2]), "r"((a)[3]), \
                   "r"((b)[0]), "r"((b)[1]))

__device__ __forceinline__ uint32_t sw128(uint32_t off) { return off ^ ((off >> 3) & 0x70); }

// split (x, y) fp32 -> packed bf16x2 hi + lo (residual)
__device__ __forceinline__ void split2(float x, float y, uint32_t& hi, uint32_t& lo) {
    __nv_bfloat16 hx = __float2bfloat16(x), hy = __float2bfloat16(y);
    __nv_bfloat162 h2 = __halves2bfloat162(hx, hy);
    __nv_bfloat162 l2 = __halves2bfloat162(__float2bfloat16(x - __bfloat162float(hx)),
                                           __float2bfloat16(y - __bfloat162float(hy)));
    hi = *reinterpret_cast<uint32_t*>(&h2);
    lo = *reinterpret_cast<uint32_t*>(&l2);
}

// ---------------------------------------------------------------------------
// Scratch (device globals)
// ---------------------------------------------------------------------------
// Per-projection A operands (0: query / attn-out, 1: key, 2: value)
__device__ __nv_bfloat16 g_Ahi[3][(size_t)M_ * DM_];
__device__ __nv_bfloat16 g_Alo[3][(size_t)M_ * DM_];
// Per-layer transposed weights (0:Wq 1:Wk 2:Wv 3:Wo), [N,K] K-contig
__device__ __nv_bfloat16 g_Whi[4][(size_t)DM_ * DM_];
__device__ __nv_bfloat16 g_Wlo[4][(size_t)DM_ * DM_];
__device__ __nv_bfloat16 g_Qhi[B_ * H_ * S_ * DK_];  // [B,H,S,64]
__device__ __nv_bfloat16 g_Qlo[B_ * H_ * S_ * DK_];
__device__ __nv_bfloat16 g_Khi[B_ * H_ * S_ * DK_];
__device__ __nv_bfloat16 g_Klo[B_ * H_ * S_ * DK_];
__device__ __nv_bfloat16 g_Vhi[B_ * H_ * S_ * DK_];
__device__ __nv_bfloat16 g_Vlo[B_ * H_ * S_ * DK_];
__device__ __nv_bfloat16 g_Vthi[B_ * H_ * DK_ * S_]; // [B,H,64,S] (V^T)
__device__ __nv_bfloat16 g_Vtlo[B_ * H_ * DK_ * S_];

// ---------------------------------------------------------------------------
// fp32 -> (hi, lo) bf16 split for all 3 inputs in one launch (blockIdx.y = which)
// ---------------------------------------------------------------------------
__global__ void __launch_bounds__(256) conv_inputs(const float4* __restrict__ s0,
                                                   const float4* __restrict__ s1,
                                                   const float4* __restrict__ s2)
{
    const int which = blockIdx.y;
    const float4* src = (which == 0) ? s0 : (which == 1) ? s1 : s2;
    uint32_t* hi = reinterpret_cast<uint32_t*>(g_Ahi[which]);
    uint32_t* lo = reinterpret_cast<uint32_t*>(g_Alo[which]);
    int i = blockIdx.x * 256 + threadIdx.x;
    float4 v = src[i];
    uint32_t h0, l0, h1, l1;
    split2(v.x, v.y, h0, l0);
    split2(v.z, v.w, h1, l1);
    hi[2 * i + 0] = h0;
    hi[2 * i + 1] = h1;
    lo[2 * i + 0] = l0;
    lo[2 * i + 1] = l1;
}

// ---------------------------------------------------------------------------
// All 4 weights: W [K,N] fp32 -> transposed split bf16 Wt[N,K]  (blockIdx.z = which)
// ---------------------------------------------------------------------------
__global__ void __launch_bounds__(256) conv_weights(const float* __restrict__ W0,
                                                    const float* __restrict__ W1,
                                                    const float* __restrict__ W2,
                                                    const float* __restrict__ W3)
{
    __shared__ float tile[32][33];
    const int which = blockIdx.z;
    const float* W = (which == 0) ? W0 : (which == 1) ? W1 : (which == 2) ? W2 : W3;
    __nv_bfloat16* hi = g_Whi[which];
    __nv_bfloat16* lo = g_Wlo[which];
    const int bx = blockIdx.x, by = blockIdx.y;
    const int tx = threadIdx.x, ty = threadIdx.y;     // 32 x 8
    #pragma unroll
    for (int j = 0; j < 32; j += 8)
        tile[ty + j][tx] = W[(size_t)(by * 32 + ty + j) * DM_ + bx * 32 + tx];
    __syncthreads();
    #pragma unroll
    for (int j = 0; j < 32; j += 8) {
        float v = tile[tx][ty + j];
        __nv_bfloat16 h = __float2bfloat16(v);
        size_t o = (size_t)(bx * 32 + ty + j) * DM_ + by * 32 + tx;
        hi[o] = h;
        lo[o] = __float2bfloat16(v - __bfloat162float(h));
    }
}

// ---------------------------------------------------------------------------
// V [B,H,S,64] hi/lo -> V^T [B,H,64,S] hi/lo
// ---------------------------------------------------------------------------
__global__ void __launch_bounds__(256) transpV()
{
    __shared__ __nv_bfloat16 th[64][65], tl[64][65];
    const int s0 = blockIdx.x * 64, bh = blockIdx.y;
    const int t = threadIdx.x;
    const __nv_bfloat16* sh_ = g_Vhi + (size_t)bh * S_ * DK_;
    const __nv_bfloat16* sl_ = g_Vlo + (size_t)bh * S_ * DK_;
    #pragma unroll
    for (int it = 0; it < 2; it++) {
        int r = (t >> 3) + it * 32, c = (t & 7) * 8;
        #pragma unroll
        for (int q = 0; q < 8; q++) {
            th[r][c + q] = sh_[(size_t)(s0 + r) * DK_ + c + q];
            tl[r][c + q] = sl_[(size_t)(s0 + r) * DK_ + c + q];
        }
    }
    __syncthreads();
    __nv_bfloat16* dh = g_Vthi + (size_t)bh * DK_ * S_;
    __nv_bfloat16* dl = g_Vtlo + (size_t)bh * DK_ * S_;
    #pragma unroll
    for (int it = 0; it < 2; it++) {
        int d = (t >> 3) + it * 32, sc = (t & 7) * 8;
        #pragma unroll
        for (int q = 0; q < 8; q++) {
            dh[(size_t)d * S_ + s0 + sc + q] = th[sc + q][d];
            dl[(size_t)d * S_ + s0 + sc + q] = tl[sc + q][d];
        }
    }
}

// ---------------------------------------------------------------------------
// HMMA GEMM: C[4096,1024] = A @ W + bias via 3 bf16 passes, 3-stage cp.async.
// modes 0/1/2 -> head-split bf16 hi/lo into Q/K/V buffers; mode 3 -> fp32 Cext.
// ---------------------------------------------------------------------------
#define GM 128
#define GN 128
#define NCH 48
#define GEMM_SMEM (3 * 32768)

__global__ void __launch_bounds__(256) gemm_mma(const __nv_bfloat16* __restrict__ Ahi,
                                                const __nv_bfloat16* __restrict__ Alo,
                                                const __nv_bfloat16* __restrict__ Whi,
                                                const __nv_bfloat16* __restrict__ Wlo,
                                                const float* __restrict__ bias,
                                                float* __restrict__ Cext, int mode)
{
    extern __shared__ __align__(1024) char smem[];
    const uint32_t sb = smem_u32(smem);
    const int t = threadIdx.x, lane = t & 31, wid = t >> 5;
    const int warpM = wid >> 1, warpN = wid & 1;
    const int row0 = blockIdx.y * GM, col0 = blockIdx.x * GN;

    float c[2][8][4] = {};

    int lr[4], lc[4];
    #pragma unroll
    for (int j = 0; j < 4; j++) {
        int g = t + j * 256;
        lr[j] = g >> 3;
        lc[j] = (g & 7) * 8;
    }

    auto issue = [&](int i) {
        const int seg = i >> 4, kc = (i & 15) * 64;
        const __nv_bfloat16* aseg = (seg == 1) ? Alo : Ahi;
        const __nv_bfloat16* wseg = (seg == 2) ? Wlo : Whi;
        const uint32_t ab = sb + (uint32_t)(i % 3) * 32768u;
        const uint32_t bb = ab + 16384u;
        #pragma unroll
        for (int j = 0; j < 4; j++) {
            uint32_t so = sw128((uint32_t)(lr[j] * 128 + lc[j] * 2));
            CP_ASYNC16(ab + so, aseg + (size_t)(row0 + lr[j]) * DM_ + kc + lc[j]);
            CP_ASYNC16(bb + so, wseg + (size_t)(col0 + lr[j]) * DM_ + kc + lc[j]);
        }
    };

    issue(0); CP_COMMIT();
    issue(1); CP_COMMIT();

    for (int i = 0; i < NCH; i++) {
        if (i + 1 < NCH) CP_WAIT(1); else CP_WAIT(0);
        __syncthreads();                       // also fences buffer (i-1) reuse
        if (i + 2 < NCH) { issue(i + 2); CP_COMMIT(); }

        const uint32_t ab = sb + (uint32_t)(i % 3) * 32768u;
        const uint32_t bb = ab + 16384u;

        #pragma unroll
        for (int kst = 0; kst < 4; kst++) {
            const int kk = kst * 16;
            uint32_t a[2][4], b[8][2];
            #pragma unroll
            for (int mt = 0; mt < 2; mt++) {
                int r = warpM * 32 + mt * 16 + (lane & 7) + ((lane >> 3) & 1) * 8;
                int kcol = kk + (lane >> 4) * 8;
                LDSM_X4(a[mt][0], a[mt][1], a[mt][2], a[mt][3],
                        ab + sw128((uint32_t)(r * 128 + kcol * 2)));
            }
            #pragma unroll
            for (int np = 0; np < 4; np++) {
                int r = warpN * 64 + np * 16 + (lane & 7) + (lane >> 4) * 8;
                int kcol = kk + ((lane >> 3) & 1) * 8;
                LDSM_X4(b[2 * np][0], b[2 * np][1], b[2 * np + 1][0], b[2 * np + 1][1],
                        bb + sw128((uint32_t)(r * 128 + kcol * 2)));
            }
            #pragma unroll
            for (int mt = 0; mt < 2; mt++)
                #pragma unroll
                for (int nt = 0; nt < 8; nt++)
                    MMA_BF16(c[mt][nt], a[mt], b[nt]);
        }
    }

    __nv_bfloat16* Hb = (mode == 0) ? g_Qhi : (mode == 1) ? g_Khi : g_Vhi;
    __nv_bfloat16* Lb = (mode == 0) ? g_Qlo : (mode == 1) ? g_Klo : g_Vlo;
    #pragma unroll
    for (int mt = 0; mt < 2; mt++) {
        #pragma unroll
        for (int half = 0; half < 2; half++) {
            const int rowg = row0 + warpM * 32 + mt * 16 + (lane >> 2) + half * 8;
            const int bb_ = rowg >> 11, ss = rowg & (S_ - 1);
            #pragma unroll
            for (int nt = 0; nt < 8; nt++) {
                const int colg = col0 + warpN * 64 + nt * 8 + (lane & 3) * 2;
                const float v0 = c[mt][nt][half * 2 + 0] + bias[colg];
                const float v1 = c[mt][nt][half * 2 + 1] + bias[colg + 1];
                if (mode < 3) {
                    const int h = colg >> 6;
                    size_t off = ((size_t)((bb_ * H_ + h) * S_ + ss)) * DK_ + (colg & 63);
                    uint32_t hiw, low;
                    split2(v0, v1, hiw, low);
                    *reinterpret_cast<uint32_t*>(Hb + off) = hiw;
                    *reinterpret_cast<uint32_t*>(Lb + off) = low;
                } else {
                    *reinterpret_cast<float2*>(Cext + (size_t)rowg * DM_ + colg) =
                        make_float2(v0, v1);
                }
            }
        }
    }
}

// ---------------------------------------------------------------------------
// HMMA flash attention, causal, hi/lo split on QK^T and PV.
// CTA = 128 query rows of one (b,h); 8 warps x 16 rows; 64 keys / iteration.
// LPT scheduling: heavy (high-qb) CTAs launch first via index reversal.
// Output: bf16 hi/lo into g_Ahi[0]/g_Alo[0] at [B,S,1024].
// ---------------------------------------------------------------------------
#define ATT_SMEM 98304

__global__ void __launch_bounds__(256, 1) attn_mma()
{
    extern __shared__ __align__(1024) char smem[];
    const uint32_t sb = smem_u32(smem);
    const int t = threadIdx.x, lane = t & 31, w = t >> 5;
    const int qb = (int)gridDim.x - 1 - (int)blockIdx.x;   // heavy-first (LPT)
    const int bh = blockIdx.y;
    const int qs = qb * 128;
    const int ntiles = qb * 2 + 2;

    const size_t bo = (size_t)bh * S_ * DK_;
    const __nv_bfloat16* Qh = g_Qhi + bo;
    const __nv_bfloat16* Ql = g_Qlo + bo;
    const __nv_bfloat16* Kh = g_Khi + bo;
    const __nv_bfloat16* Kl = g_Klo + bo;
    const __nv_bfloat16* Vh = g_Vthi + (size_t)bh * DK_ * S_;
    const __nv_bfloat16* Vl = g_Vtlo + (size_t)bh * DK_ * S_;

    const uint32_t QH = sb, QL = sb + 16384;

    #pragma unroll
    for (int j = 0; j < 4; j++) {
        int g = t + j * 256, r = g >> 3, c = (g & 7) * 8;
        uint32_t so = sw128((uint32_t)(r * 128 + c * 2));
        CP_ASYNC16(QH + so, Qh + (size_t)(qs + r) * DK_ + c);
        CP_ASYNC16(QL + so, Ql + (size_t)(qs + r) * DK_ + c);
    }
    auto issueKV = [&](int i) {
        const int kt = i * 64;
        const uint32_t bB = sb + 32768u + (uint32_t)(i & 1) * 32768u;
        #pragma unroll
        for (int j = 0; j < 2; j++) {
            int g = t + j * 256, r = g >> 3, c = (g & 7) * 8;
            uint32_t so = sw128((uint32_t)(r * 128 + c * 2));
            CP_ASYNC16(bB + so,         Kh + (size_t)(kt + r) * DK_ + c);
            CP_ASYNC16(bB + 8192 + so,  Kl + (size_t)(kt + r) * DK_ + c);
            CP_ASYNC16(bB + 16384 + so, Vh + (size_t)r * S_ + kt + c);
            CP_ASYNC16(bB + 24576 + so, Vl + (size_t)r * S_ + kt + c);
        }
    };
    issueKV(0);
    CP_COMMIT();
    if (ntiles > 1) { issueKV(1); CP_COMMIT(); }

    uint32_t qhf[4][4], qlf[4][4];
    float o[8][4] = {};
    float mrow0 = -INFINITY, mrow1 = -INFINITY, lrow0 = 0.f, lrow1 = 0.f;

    for (int i = 0; i < ntiles; i++) {
        if (i + 1 < ntiles) CP_WAIT(1); else CP_WAIT(0);
        __syncthreads();

        if (i == 0) {
            #pragma unroll
            for (int kc = 0; kc < 4; kc++) {
                int r = w * 16 + (lane & 7) + ((lane >> 3) & 1) * 8;
                int kcol = kc * 16 + (lane >> 4) * 8;
                uint32_t so = sw128((uint32_t)(r * 128 + kcol * 2));
                LDSM_X4(qhf[kc][0], qhf[kc][1], qhf[kc][2], qhf[kc][3], QH + so);
                LDSM_X4(qlf[kc][0], qlf[kc][1], qlf[kc][2], qlf[kc][3], QL + so);
            }
        }

        const int kt = i * 64;
        const uint32_t bB = sb + 32768u + (uint32_t)(i & 1) * 32768u;

        // ---- S = Qhi*Khi + Qlo*Khi + Qhi*Klo
        float s[8][4] = {};
        #pragma unroll
        for (int kc = 0; kc < 4; kc++) {
            const int kk = kc * 16;
            uint32_t bf[8][2];
            #pragma unroll
            for (int np = 0; np < 4; np++) {
                int r = np * 16 + (lane & 7) + (lane >> 4) * 8;
                int kcol = kk + ((lane >> 3) & 1) * 8;
                LDSM_X4(bf[2 * np][0], bf[2 * np][1], bf[2 * np + 1][0], bf[2 * np + 1][1],
                        bB + sw128((uint32_t)(r * 128 + kcol * 2)));
            }
            #pragma unroll
            for (int j = 0; j < 8; j++) {
                MMA_BF16(s[j], qhf[kc], bf[j]);
                MMA_BF16(s[j], qlf[kc], bf[j]);
            }
            #pragma unroll
            for (int np = 0; np < 4; np++) {
                int r = np * 16 + (lane & 7) + (lane >> 4) * 8;
                int kcol = kk + ((lane >> 3) & 1) * 8;
                LDSM_X4(bf[2 * np][0], bf[2 * np][1], bf[2 * np + 1][0], bf[2 * np + 1][1],
                        bB + 8192 + sw128((uint32_t)(r * 128 + kcol * 2)));
            }
            #pragma unroll
            for (int j = 0; j < 8; j++)
                MMA_BF16(s[j], qhf[kc], bf[j]);
        }

        // ---- scale + causal mask + online softmax
        const int r0g = qs + w * 16 + (lane >> 2);
        const bool needmask = (kt + 63 > qs + w * 16);
        float mx0 = -INFINITY, mx1 = -INFINITY;
        #pragma unroll
        for (int j = 0; j < 8; j++) {
            const int cg = kt + j * 8 + (lane & 3) * 2;
            float v0 = s[j][0] * 0.125f, v1 = s[j][1] * 0.125f;
            float v2 = s[j][2] * 0.125f, v3 = s[j][3] * 0.125f;
            if (needmask) {
                if (cg     > r0g)     v0 = -INFINITY;
                if (cg + 1 > r0g)     v1 = -INFINITY;
                if (cg     > r0g + 8) v2 = -INFINITY;
                if (cg + 1 > r0g + 8) v3 = -INFINITY;
            }
            s[j][0] = v0; s[j][1] = v1; s[j][2] = v2; s[j][3] = v3;
            mx0 = fmaxf(mx0, fmaxf(v0, v1));
            mx1 = fmaxf(mx1, fmaxf(v2, v3));
        }
        mx0 = fmaxf(mx0, __shfl_xor_sync(0xffffffffu, mx0, 1));
        mx0 = fmaxf(mx0, __shfl_xor_sync(0xffffffffu, mx0, 2));
        mx1 = fmaxf(mx1, __shfl_xor_sync(0xffffffffu, mx1, 1));
        mx1 = fmaxf(mx1, __shfl_xor_sync(0xffffffffu, mx1, 2));
        const float mn0 = fmaxf(mrow0, mx0), mn1 = fmaxf(mrow1, mx1);
        const float al0 = __expf(mrow0 - mn0), al1 = __expf(mrow1 - mn1);
        float sum0 = 0.f, sum1 = 0.f;
        #pragma unroll
        for (int j = 0; j < 8; j++) {
            float p0 = __expf(s[j][0] - mn0); s[j][0] = p0; sum0 += p0;
            float p1 = __expf(s[j][1] - mn0); s[j][1] = p1; sum0 += p1;
            float p2 = __expf(s[j][2] - mn1); s[j][2] = p2; sum1 += p2;
            float p3 = __expf(s[j][3] - mn1); s[j][3] = p3; sum1 += p3;
        }
        sum0 += __shfl_xor_sync(0xffffffffu, sum0, 1);
        sum0 += __shfl_xor_sync(0xffffffffu, sum0, 2);
        sum1 += __shfl_xor_sync(0xffffffffu, sum1, 1);
        sum1 += __shfl_xor_sync(0xffffffffu, sum1, 2);
        lrow0 = lrow0 * al0 + sum0;
        lrow1 = lrow1 * al1 + sum1;
        mrow0 = mn0; mrow1 = mn1;
        #pragma unroll
        for (int j = 0; j < 8; j++) {
            o[j][0] *= al0; o[j][1] *= al0;
            o[j][2] *= al1; o[j][3] *= al1;
        }

        // ---- P -> bf16 hi/lo A-fragments (in-register)
        uint32_t phi[4][4], plo[4][4];
        #pragma unroll
        for (int kc = 0; kc < 4; kc++) {
            split2(s[2 * kc][0],     s[2 * kc][1],     phi[kc][0], plo[kc][0]);
            split2(s[2 * kc][2],     s[2 * kc][3],     phi[kc][1], plo[kc][1]);
            split2(s[2 * kc + 1][0], s[2 * kc + 1][1], phi[kc][2], plo[kc][2]);
            split2(s[2 * kc + 1][2], s[2 * kc + 1][3], phi[kc][3], plo[kc][3]);
        }

        // ---- O += Phi*Vhi + Plo*Vhi + Phi*Vlo
        #pragma unroll
        for (int kc = 0; kc < 4; kc++) {
            const int kk = kc * 16;
            uint32_t bf[8][2];
            #pragma unroll
            for (int np = 0; np < 4; np++) {
                int r = np * 16 + (lane & 7) + (lane >> 4) * 8;
                int kcol = kk + ((lane >> 3) & 1) * 8;
                LDSM_X4(bf[2 * np][0], bf[2 * np][1], bf[2 * np + 1][0], bf[2 * np + 1][1],
                        bB + 16384 + sw128((uint32_t)(r * 128 + kcol * 2)));
            }
            #pragma unroll
            for (int j = 0; j < 8; j++) {
                MMA_BF16(o[j], phi[kc], bf[j]);
                MMA_BF16(o[j], plo[kc], bf[j]);
            }
            #pragma unroll
            for (int np = 0; np < 4; np++) {
                int r = np * 16 + (lane & 7) + (lane >> 4) * 8;
                int kcol = kk + ((lane >> 3) & 1) * 8;
                LDSM_X4(bf[2 * np][0], bf[2 * np][1], bf[2 * np + 1][0], bf[2 * np + 1][1],
                        bB + 24576 + sw128((uint32_t)(r * 128 + kcol * 2)));
            }
            #pragma unroll
            for (int j = 0; j < 8; j++)
                MMA_BF16(o[j], phi[kc], bf[j]);
        }

        __syncthreads();
        if (i + 2 < ntiles) { issueKV(i + 2); CP_COMMIT(); }
    }

    // ---- epilogue: normalize and write bf16 hi/lo to [B,S,1024]
    const float inv0 = 1.0f / lrow0, inv1 = 1.0f / lrow1;
    const int b = bh >> 4, h = bh & 15;
    const int row0g = qs + w * 16 + (lane >> 2);
    #pragma unroll
    for (int j = 0; j < 8; j++) {
        const int d = j * 8 + (lane & 3) * 2;
        size_t off0 = (size_t)(b * S_ + row0g) * DM_ + h * DK_ + d;
        size_t off1 = off0 + (size_t)8 * DM_;
        uint32_t hiw, low;
        split2(o[j][0] * inv0, o[j][1] * inv0, hiw, low);
        *reinterpret_cast<uint32_t*>(g_Ahi[0] + off0) = hiw;
        *reinterpret_cast<uint32_t*>(g_Alo[0] + off0) = low;
        split2(o[j][2] * inv1, o[j][3] * inv1, hiw, low);
        *reinterpret_cast<uint32_t*>(g_Ahi[0] + off1) = hiw;
        *reinterpret_cast<uint32_t*>(g_Alo[0] + off1) = low;
    }
}

// ----------------------------------------------------------------------------
extern "C" void kernel_launch(void* const* d_in, const int* in_sizes, int n_in,
                              void* d_out, int out_size)
{
    const float* query = (const float*)d_in[0];
    const float* key   = (const float*)d_in[1];
    const float* value = (const float*)d_in[2];
    const float* Wq = (const float*)d_in[4];
    const float* bq = (const float*)d_in[5];
    const float* Wk = (const float*)d_in[6];
    const float* bk = (const float*)d_in[7];
    const float* Wv = (const float*)d_in[8];
    const float* bv = (const float*)d_in[9];
    const float* Wo = (const float*)d_in[10];
    const float* bo = (const float*)d_in[11];
    float* out = (float*)d_out;

    cudaFuncSetAttribute(gemm_mma, cudaFuncAttributeMaxDynamicSharedMemorySize, GEMM_SMEM);
    cudaFuncSetAttribute(attn_mma, cudaFuncAttributeMaxDynamicSharedMemorySize, ATT_SMEM);

    const int n4 = M_ * DM_ / 4;
    const dim3 gg(DM_ / GN, M_ / GM);

    __nv_bfloat16 *Ahi, *Alo, *Whi, *Wlo;
    cudaGetSymbolAddress((void**)&Ahi, g_Ahi);
    cudaGetSymbolAddress((void**)&Alo, g_Alo);
    cudaGetSymbolAddress((void**)&Whi, g_Whi);
    cudaGetSymbolAddress((void**)&Wlo, g_Wlo);
    const size_t AS = (size_t)M_ * DM_;
    const size_t WS = (size_t)DM_ * DM_;

    // All conversions up front (independent)
    conv_inputs<<<dim3(n4 / 256, 3), 256>>>((const float4*)query, (const float4*)key,
                                            (const float4*)value);
    conv_weights<<<dim3(32, 32, 4), dim3(32, 8)>>>(Wq, Wk, Wv, Wo);

    // Projections
    gemm_mma<<<gg, 256, GEMM_SMEM>>>(Ahi + 0 * AS, Alo + 0 * AS, Whi + 0 * WS, Wlo + 0 * WS, bq, nullptr, 0);
    gemm_mma<<<gg, 256, GEMM_SMEM>>>(Ahi + 1 * AS, Alo + 1 * AS, Whi + 1 * WS, Wlo + 1 * WS, bk, nullptr, 1);
    gemm_mma<<<gg, 256, GEMM_SMEM>>>(Ahi + 2 * AS, Alo + 2 * AS, Whi + 2 * WS, Wlo + 2 * WS, bv, nullptr, 2);
    transpV<<<dim3(S_ / 64, B_ * H_), 256>>>();
    // Attention (writes g_Ahi[0]/g_Alo[0])
    attn_mma<<<dim3(S_ / 128, B_ * H_), 256, ATT_SMEM>>>();
    // Output projection
    gemm_mma<<<gg, 256, GEMM_SMEM>>>(Ahi + 0 * AS, Alo + 0 * AS, Whi + 3 * WS, Wlo + 3 * WS, bo, out, 3);
}